// round 1
// baseline (speedup 1.0000x reference)
#include <cuda_runtime.h>
#include <math.h>

#define N_NODES 100000
#define B_GRAPHS 128
#define H 8
#define DC 256
#define DX 128   /* DE+4 */
#define DV 64
#define DOUT 124

// ---- scratch (static device globals; no allocation) ----
__device__ float g_query[H * B_GRAPHS * DV];   // 256 KB
__device__ float g_kq[H * B_GRAPHS * DX];      // 512 KB  (Wk @ q, scaled by 1/sqrt(DV))
__device__ float g_u[H * N_NODES];             // 3.2 MB  (u, then overwritten by e)
__device__ float g_inv[H * B_GRAPHS];          // 1/(segsum+1e-16)
__device__ float g_xa[H * B_GRAPHS * DX];      // 512 KB  (sum_n a*x)
__device__ int   g_segstart[B_GRAPHS + 1];

// ---------------------------------------------------------------------------
// Kernel 1: segment boundaries from sorted batch[] + zero g_xa
// ---------------------------------------------------------------------------
__global__ void k_init(const int* __restrict__ batch) {
    int i = blockIdx.x * blockDim.x + threadIdx.x;
    if (i < H * B_GRAPHS * DX) g_xa[i] = 0.0f;
    if (i < N_NODES) {
        int b  = batch[i];
        int bp = (i == 0) ? -1 : batch[i - 1];
        for (int j = bp + 1; j <= b; j++) g_segstart[j] = i;
        if (i == N_NODES - 1)
            for (int j = b + 1; j <= B_GRAPHS; j++) g_segstart[j] = N_NODES;
    }
}

// ---------------------------------------------------------------------------
// Kernel 2: query[h,b,v] = context[b] @ Wq[h];  kq[h,b,e] = (Wk[h] @ q)/8
// grid = H*B blocks, 128 threads
// ---------------------------------------------------------------------------
__global__ void k_qkq(const float* __restrict__ context,
                      const float* __restrict__ Wq,
                      const float* __restrict__ Wk) {
    int h = blockIdx.x / B_GRAPHS;
    int b = blockIdx.x % B_GRAPHS;
    int t = threadIdx.x;
    __shared__ float q_s[DV];

    if (t < DV) {
        float acc = 0.0f;
        const float* ctx = context + b * DC;
        const float* wq  = Wq + h * DC * DV + t;
#pragma unroll 8
        for (int c = 0; c < DC; c++) acc += ctx[c] * wq[c * DV];
        q_s[t] = acc;
        g_query[(h * B_GRAPHS + b) * DV + t] = acc;
    }
    __syncthreads();
    {
        float acc = 0.0f;
        const float* wk = Wk + (h * DX + t) * DV;
#pragma unroll 8
        for (int v = 0; v < DV; v++) acc += wk[v] * q_s[v];
        g_kq[(h * B_GRAPHS + b) * DX + t] = acc * 0.125f;  // 1/sqrt(64)
    }
}

// ---------------------------------------------------------------------------
// Kernel 3: u[h,n] = x[n] . kq[h, batch[n]]    (warp per node)
// ---------------------------------------------------------------------------
__global__ void k_u(const float* __restrict__ x, const int* __restrict__ batch) {
    int warp = threadIdx.x >> 5;
    int lane = threadIdx.x & 31;
    int n = blockIdx.x * 8 + warp;
    if (n >= N_NODES) return;

    float4 xv = ((const float4*)(x + (long long)n * DX))[lane];
    int b = batch[n];

#pragma unroll
    for (int h = 0; h < H; h++) {
        float4 kv = ((const float4*)(g_kq + (h * B_GRAPHS + b) * DX))[lane];
        float p = xv.x * kv.x + xv.y * kv.y + xv.z * kv.z + xv.w * kv.w;
#pragma unroll
        for (int off = 16; off; off >>= 1)
            p += __shfl_xor_sync(0xffffffffu, p, off);
        if (lane == 0) g_u[h * N_NODES + n] = p;
    }
}

// ---------------------------------------------------------------------------
// Kernel 4: per-(h,graph) softmax over contiguous segment:
//   max, then e=exp(u-max) stored in place, then inv = 1/(sum+1e-16)
// grid = H*B blocks, 256 threads
// ---------------------------------------------------------------------------
__global__ void k_softmax() {
    int h = blockIdx.x / B_GRAPHS;
    int b = blockIdx.x % B_GRAPHS;
    int t = threadIdx.x;
    int s0 = g_segstart[b], s1 = g_segstart[b + 1];
    float* u = g_u + h * N_NODES;

    __shared__ float red[8];
    __shared__ float bcast;

    float m = -INFINITY;
    for (int i = s0 + t; i < s1; i += 256) m = fmaxf(m, u[i]);
#pragma unroll
    for (int off = 16; off; off >>= 1)
        m = fmaxf(m, __shfl_xor_sync(0xffffffffu, m, off));
    if ((t & 31) == 0) red[t >> 5] = m;
    __syncthreads();
    if (t == 0) {
        float mm = red[0];
        for (int w = 1; w < 8; w++) mm = fmaxf(mm, red[w]);
        bcast = mm;
    }
    __syncthreads();
    float mx = bcast;

    float s = 0.0f;
    for (int i = s0 + t; i < s1; i += 256) {
        float e = expf(u[i] - mx);
        u[i] = e;
        s += e;
    }
#pragma unroll
    for (int off = 16; off; off >>= 1)
        s += __shfl_xor_sync(0xffffffffu, s, off);
    __syncthreads();
    if ((t & 31) == 0) red[t >> 5] = s;
    __syncthreads();
    if (t == 0) {
        float ss = 0.0f;
        for (int w = 0; w < 8; w++) ss += red[w];
        g_inv[h * B_GRAPHS + b] = 1.0f / (ss + 1e-16f);
    }
}

// ---------------------------------------------------------------------------
// Kernel 5: xa[h,g,e] = sum_{n in seg(g)} a[h,n] * x[n,e]
// grid = B*8 blocks (8 slices per graph), 256 threads;
// thread t owns head t/32, e-range (t%32)*4 .. +3 in registers; atomic flush.
// ---------------------------------------------------------------------------
__global__ void k_xa(const float* __restrict__ x) {
    int g = blockIdx.x >> 3;
    int s = blockIdx.x & 7;
    int t = threadIdx.x;
    int s0 = g_segstart[g], s1 = g_segstart[g + 1];
    int len = s1 - s0;
    int chunk = (len + 7) >> 3;
    int lo = s0 + s * chunk;
    int hi = min(lo + chunk, s1);

    __shared__ float xs[DX];
    __shared__ float as_[H];

    int hh = t >> 5;
    int e4 = (t & 31) << 2;
    float4 acc = make_float4(0.f, 0.f, 0.f, 0.f);

    for (int n = lo; n < hi; n++) {
        if (t < DX) xs[t] = x[(long long)n * DX + t];
        if (t >= DX && t < DX + H) {
            int h2 = t - DX;
            as_[h2] = g_u[h2 * N_NODES + n] * g_inv[h2 * B_GRAPHS + g];
        }
        __syncthreads();
        float a = as_[hh];
        float4 xv = *(const float4*)(xs + e4);
        acc.x += a * xv.x;
        acc.y += a * xv.y;
        acc.z += a * xv.z;
        acc.w += a * xv.w;
        __syncthreads();
    }

    float* dst = g_xa + (hh * B_GRAPHS + g) * DX + e4;
    atomicAdd(dst + 0, acc.x);
    atomicAdd(dst + 1, acc.y);
    atomicAdd(dst + 2, acc.z);
    atomicAdd(dst + 3, acc.w);
}

// ---------------------------------------------------------------------------
// Kernel 6: out[b,:] = (sum_h qc*query[h,b] + xa[h,b] @ Wv[h]) @ Wf
// grid = B blocks, 128 threads
// ---------------------------------------------------------------------------
__global__ void k_final(const float* __restrict__ Wv,
                        const float* __restrict__ qcoef,
                        const float* __restrict__ Wf,
                        float* __restrict__ out) {
    int b = blockIdx.x;
    int t = threadIdx.x;
    float qc = qcoef[0];

    __shared__ float gs0[DV];
    __shared__ float gs1[DV];

    int v  = t & 63;
    int h0 = (t >> 6) * 4;

    float local = 0.0f;
#pragma unroll
    for (int i = 0; i < 4; i++) {
        int h  = h0 + i;
        int hb = h * B_GRAPHS + b;
        float acc = qc * g_query[hb * DV + v];
        const float* xa = g_xa + hb * DX;
        const float* wv = Wv + h * DX * DV + v;
#pragma unroll 4
        for (int e = 0; e < DX; e++) acc += xa[e] * wv[e * DV];
        local += acc;
    }
    if (t < DV) gs0[v] = local; else gs1[v] = local;
    __syncthreads();

    if (t < DOUT) {
        float acc = 0.0f;
#pragma unroll 8
        for (int v2 = 0; v2 < DV; v2++)
            acc += (gs0[v2] + gs1[v2]) * Wf[v2 * DOUT + t];
        out[b * DOUT + t] = acc;
    }
}

// ---------------------------------------------------------------------------
extern "C" void kernel_launch(void* const* d_in, const int* in_sizes, int n_in,
                              void* d_out, int out_size) {
    const float* x       = (const float*)d_in[0];
    // d_in[1] = edge_index (unused by the reference math)
    const int*   batch   = (const int*)d_in[2];
    const float* context = (const float*)d_in[3];
    const float* Wq      = (const float*)d_in[4];
    const float* Wk      = (const float*)d_in[5];
    const float* Wv      = (const float*)d_in[6];
    const float* qcoef   = (const float*)d_in[7];
    const float* Wf      = (const float*)d_in[8];
    float* out = (float*)d_out;

    k_init<<<512, 256>>>(batch);                       // 131072 threads
    k_qkq<<<H * B_GRAPHS, 128>>>(context, Wq, Wk);
    k_u<<<(N_NODES + 7) / 8, 256>>>(x, batch);
    k_softmax<<<H * B_GRAPHS, 256>>>();
    k_xa<<<B_GRAPHS * 8, 256>>>(x);
    k_final<<<B_GRAPHS, 128>>>(Wv, qcoef, Wf, out);
}

// round 2
// speedup vs baseline: 1.2711x; 1.2711x over previous
#include <cuda_runtime.h>
#include <math.h>

#define N_NODES 100000
#define B_GRAPHS 128
#define H 8
#define DC 256
#define DX 128   /* DE+4 */
#define DV 64
#define DOUT 124
#define S_SLICES 16
#define CHUNK 16

// ---- scratch (static device globals; no allocation) ----
__device__ __align__(16) float g_query[H * B_GRAPHS * DV];           // 256 KB
__device__ __align__(16) float g_kq[H * B_GRAPHS * DX];              // 512 KB (Wk@q / 8)
__device__ __align__(16) float g_xa[H * B_GRAPHS * DX];              // 512 KB
__device__ __align__(16) float g_part_xa[S_SLICES * H * B_GRAPHS * DX]; // 8 MB
__device__ float g_part_m[S_SLICES * H * B_GRAPHS];
__device__ float g_part_s[S_SLICES * H * B_GRAPHS];
__device__ int   g_segstart[B_GRAPHS + 1];

// ---------------------------------------------------------------------------
// Kernel 1: segment boundaries from sorted batch[]
// ---------------------------------------------------------------------------
__global__ void k_init(const int* __restrict__ batch) {
    int i = blockIdx.x * blockDim.x + threadIdx.x;
    if (i < N_NODES) {
        int b  = batch[i];
        int bp = (i == 0) ? -1 : batch[i - 1];
        for (int j = bp + 1; j <= b; j++) g_segstart[j] = i;
        if (i == N_NODES - 1)
            for (int j = b + 1; j <= B_GRAPHS; j++) g_segstart[j] = N_NODES;
    }
}

// ---------------------------------------------------------------------------
// Kernel 2: query[h,b,v] = context[b] @ Wq[h];  kq[h,b,e] = (Wk[h] @ q)/8
// ---------------------------------------------------------------------------
__global__ void k_qkq(const float* __restrict__ context,
                      const float* __restrict__ Wq,
                      const float* __restrict__ Wk) {
    int h = blockIdx.x / B_GRAPHS;
    int b = blockIdx.x % B_GRAPHS;
    int t = threadIdx.x;
    __shared__ float q_s[DV];

    if (t < DV) {
        float acc = 0.0f;
        const float* ctx = context + b * DC;
        const float* wq  = Wq + h * DC * DV + t;
#pragma unroll 8
        for (int c = 0; c < DC; c++) acc += ctx[c] * wq[c * DV];
        q_s[t] = acc;
        g_query[(h * B_GRAPHS + b) * DV + t] = acc;
    }
    __syncthreads();
    {
        float acc = 0.0f;
        const float* wk = Wk + (h * DX + t) * DV;
#pragma unroll 8
        for (int v = 0; v < DV; v++) acc += wk[v] * q_s[v];
        g_kq[(h * B_GRAPHS + b) * DX + t] = acc * 0.125f;  // 1/sqrt(64)
    }
}

// ---------------------------------------------------------------------------
// Kernel 3 (fused): per (graph, slice) block, single pass over x:
//   u = x . kq  -> online softmax (running max/sum) -> acc += e * x
// Warp w == head w. kq in registers (float4 per lane).
// Partials (m, sum, acc) written per slice; combined exactly in k_combine.
// ---------------------------------------------------------------------------
__global__ __launch_bounds__(256) void k_fused(const float* __restrict__ x) {
    int s = blockIdx.x;          // slice
    int g = blockIdx.y;          // graph
    int t = threadIdx.x;
    int h = t >> 5;
    int lane = t & 31;

    int s0 = g_segstart[g], s1 = g_segstart[g + 1];
    int len = s1 - s0;
    int per = (len + S_SLICES - 1) / S_SLICES;
    int lo = s0 + s * per;
    int hi = min(lo + per, s1);

    __shared__ float4 xs4[CHUNK * 32];   // 16 nodes x 128 floats = 8 KB

    float4 rkq = ((const float4*)(g_kq + (h * B_GRAPHS + g) * DX))[lane];

    float4 acc = make_float4(0.f, 0.f, 0.f, 0.f);
    float m_run = -INFINITY;
    float s_run = 0.0f;

    const float4* xg = (const float4*)x;

    for (int c0 = lo; c0 < hi; c0 += CHUNK) {
        int cnt = min(CHUNK, hi - c0);

        // stage chunk of x (coalesced: warp covers one node row)
#pragma unroll
        for (int k = 0; k < 2; k++) {
            int f = t + k * 256;
            int node = f >> 5;
            if (node < cnt) xs4[f] = xg[(size_t)(c0 + node) * 32 + (f & 31)];
        }
        __syncthreads();

        // ---- u phase: warp h computes u for all cnt nodes; lane n keeps u[n]
        float un = -INFINITY;
        for (int n = 0; n < cnt; n++) {
            float4 xv = xs4[n * 32 + lane];
            float p = rkq.x * xv.x;
            p = fmaf(rkq.y, xv.y, p);
            p = fmaf(rkq.z, xv.z, p);
            p = fmaf(rkq.w, xv.w, p);
#pragma unroll
            for (int off = 16; off; off >>= 1)
                p += __shfl_xor_sync(0xffffffffu, p, off);
            if (lane == n) un = p;
        }

        // ---- online softmax update (all lanes hold identical m/s state)
        float mc = un;
#pragma unroll
        for (int off = 16; off; off >>= 1)
            mc = fmaxf(mc, __shfl_xor_sync(0xffffffffu, mc, off));
        float m_new = fmaxf(m_run, mc);
        float scale = __expf(m_run - m_new);           // 0 on first chunk
        float en = (lane < cnt) ? __expf(un - m_new) : 0.0f;
        float sc = en;
#pragma unroll
        for (int off = 16; off; off >>= 1)
            sc += __shfl_xor_sync(0xffffffffu, sc, off);
        s_run = fmaf(s_run, scale, sc);
        acc.x *= scale; acc.y *= scale; acc.z *= scale; acc.w *= scale;
        m_run = m_new;

        // ---- xa phase: acc += e_n * x[n]
        for (int n = 0; n < cnt; n++) {
            float a = __shfl_sync(0xffffffffu, en, n);
            float4 xv = xs4[n * 32 + lane];
            acc.x = fmaf(a, xv.x, acc.x);
            acc.y = fmaf(a, xv.y, acc.y);
            acc.z = fmaf(a, xv.z, acc.z);
            acc.w = fmaf(a, xv.w, acc.w);
        }
        __syncthreads();
    }

    int idx = (s * H + h) * B_GRAPHS + g;
    if (lane == 0) {
        g_part_m[idx] = m_run;
        g_part_s[idx] = s_run;
    }
    ((float4*)(g_part_xa + (size_t)idx * DX))[lane] = acc;
}

// ---------------------------------------------------------------------------
// Kernel 4: combine slice partials:
//   m* = max_s m_s;  S = sum_s s_s*exp(m_s-m*);
//   g_xa = (sum_s acc_s*exp(m_s-m*)) / (S + 1e-16)
// grid = H*B blocks, 128 threads
// ---------------------------------------------------------------------------
__global__ void k_combine() {
    int h = blockIdx.x / B_GRAPHS;
    int g = blockIdx.x % B_GRAPHS;
    int t = threadIdx.x;

    __shared__ float ms[S_SLICES], ss[S_SLICES], w[S_SLICES];
    __shared__ float inv_s;

    if (t < S_SLICES) {
        int idx = (t * H + h) * B_GRAPHS + g;
        ms[t] = g_part_m[idx];
        ss[t] = g_part_s[idx];
    }
    __syncthreads();
    if (t == 0) {
        float m = -INFINITY;
#pragma unroll
        for (int i = 0; i < S_SLICES; i++) m = fmaxf(m, ms[i]);
        float ssum = 0.0f;
#pragma unroll
        for (int i = 0; i < S_SLICES; i++) {
            float wi = (m == -INFINITY) ? 0.0f : __expf(ms[i] - m);
            w[i] = wi;
            ssum = fmaf(ss[i], wi, ssum);
        }
        inv_s = 1.0f / (ssum + 1e-16f);
    }
    __syncthreads();

    float acc = 0.0f;
#pragma unroll
    for (int i = 0; i < S_SLICES; i++)
        acc = fmaf(g_part_xa[(size_t)((i * H + h) * B_GRAPHS + g) * DX + t], w[i], acc);
    g_xa[(h * B_GRAPHS + g) * DX + t] = acc * inv_s;
}

// ---------------------------------------------------------------------------
// Kernel 5: out[b,:] = (sum_h qc*query[h,b] + xa[h,b] @ Wv[h]) @ Wf
// ---------------------------------------------------------------------------
__global__ void k_final(const float* __restrict__ Wv,
                        const float* __restrict__ qcoef,
                        const float* __restrict__ Wf,
                        float* __restrict__ out) {
    int b = blockIdx.x;
    int t = threadIdx.x;
    float qc = qcoef[0];

    __shared__ float gs0[DV];
    __shared__ float gs1[DV];

    int v  = t & 63;
    int h0 = (t >> 6) * 4;

    float local = 0.0f;
#pragma unroll
    for (int i = 0; i < 4; i++) {
        int h  = h0 + i;
        int hb = h * B_GRAPHS + b;
        float acc = qc * g_query[hb * DV + v];
        const float* xa = g_xa + hb * DX;
        const float* wv = Wv + h * DX * DV + v;
#pragma unroll 4
        for (int e = 0; e < DX; e++) acc += xa[e] * wv[e * DV];
        local += acc;
    }
    if (t < DV) gs0[v] = local; else gs1[v] = local;
    __syncthreads();

    if (t < DOUT) {
        float acc = 0.0f;
#pragma unroll 8
        for (int v2 = 0; v2 < DV; v2++)
            acc += (gs0[v2] + gs1[v2]) * Wf[v2 * DOUT + t];
        out[b * DOUT + t] = acc;
    }
}

// ---------------------------------------------------------------------------
extern "C" void kernel_launch(void* const* d_in, const int* in_sizes, int n_in,
                              void* d_out, int out_size) {
    const float* x       = (const float*)d_in[0];
    // d_in[1] = edge_index (unused by the reference math)
    const int*   batch   = (const int*)d_in[2];
    const float* context = (const float*)d_in[3];
    const float* Wq      = (const float*)d_in[4];
    const float* Wk      = (const float*)d_in[5];
    const float* Wv      = (const float*)d_in[6];
    const float* qcoef   = (const float*)d_in[7];
    const float* Wf      = (const float*)d_in[8];
    float* out = (float*)d_out;

    k_init<<<(N_NODES + 255) / 256, 256>>>(batch);
    k_qkq<<<H * B_GRAPHS, 128>>>(context, Wq, Wk);
    dim3 fgrid(S_SLICES, B_GRAPHS);
    k_fused<<<fgrid, 256>>>(x);
    k_combine<<<H * B_GRAPHS, 128>>>();
    k_final<<<B_GRAPHS, 128>>>(Wv, qcoef, Wf, out);
}

// round 3
// speedup vs baseline: 1.5482x; 1.2180x over previous
#include <cuda_runtime.h>
#include <math.h>

#define N_NODES 100000
#define B_GRAPHS 128
#define H 8
#define DC 256
#define DX 128   /* DE+4 */
#define DV 64
#define DOUT 124
#define S_SLICES 8
#define CHUNK 32

// ---- scratch (static device globals; no allocation) ----
__device__ __align__(16) float g_query[H * B_GRAPHS * DV];
__device__ __align__(16) float g_kq[H * B_GRAPHS * DX];
__device__ __align__(16) float g_xa[H * B_GRAPHS * DX];
__device__ __align__(16) float g_part_xa[S_SLICES * H * B_GRAPHS * DX]; // 4 MB
__device__ float g_part_m[S_SLICES * H * B_GRAPHS];
__device__ float g_part_s[S_SLICES * H * B_GRAPHS];
__device__ int   g_segstart[B_GRAPHS + 1];

// ---------------------------------------------------------------------------
// Kernel 1: segment boundaries from sorted batch[]
// ---------------------------------------------------------------------------
__global__ void k_init(const int* __restrict__ batch) {
    int i = blockIdx.x * blockDim.x + threadIdx.x;
    if (i < N_NODES) {
        int b  = batch[i];
        int bp = (i == 0) ? -1 : batch[i - 1];
        for (int j = bp + 1; j <= b; j++) g_segstart[j] = i;
        if (i == N_NODES - 1)
            for (int j = b + 1; j <= B_GRAPHS; j++) g_segstart[j] = N_NODES;
    }
}

// ---------------------------------------------------------------------------
// Kernel 2: query[h,b,v] = context[b] @ Wq[h];  kq[h,b,e] = (Wk[h] @ q)/8
// 128 threads: phase1 split-K (2 halves of DC), phase2 as before.
// ---------------------------------------------------------------------------
__global__ void k_qkq(const float* __restrict__ context,
                      const float* __restrict__ Wq,
                      const float* __restrict__ Wk) {
    int h = blockIdx.x / B_GRAPHS;
    int b = blockIdx.x % B_GRAPHS;
    int t = threadIdx.x;
    int v = t & 63, half = t >> 6;
    __shared__ float q_part[128];
    __shared__ float q_s[DV];

    {
        float acc = 0.0f;
        const float* ctx = context + b * DC + half * 128;
        const float* wq  = Wq + h * DC * DV + half * 128 * DV + v;
#pragma unroll 8
        for (int c = 0; c < 128; c++) acc = fmaf(ctx[c], wq[c * DV], acc);
        q_part[t] = acc;
    }
    __syncthreads();
    if (t < DV) {
        float q = q_part[t] + q_part[t + 64];
        q_s[t] = q;
        g_query[(h * B_GRAPHS + b) * DV + t] = q;
    }
    __syncthreads();
    {
        float acc = 0.0f;
        const float* wk = Wk + (h * DX + t) * DV;
#pragma unroll 8
        for (int vv = 0; vv < DV; vv++) acc = fmaf(wk[vv], q_s[vv], acc);
        g_kq[(h * B_GRAPHS + b) * DX + t] = acc * 0.125f;  // 1/sqrt(64)
    }
}

// ---------------------------------------------------------------------------
// Kernel 3 (fused): one pass over x per (graph, slice) block.
// 256 threads = 8 warps. Warp w owns e-range [16w,16w+16). lane=(h,e4):
// h=lane>>2 (head), e4=lane&3 (float4 within e-range).
// kq fragment + xa accumulator in registers. Online softmax per chunk,
// finalized by warp h (=w) with bank-padded smem reductions.
// ---------------------------------------------------------------------------
__global__ __launch_bounds__(256) void k_fused(const float* __restrict__ x) {
    const int s = blockIdx.x;
    const int g = blockIdx.y;
    const int t = threadIdx.x;
    const int w = t >> 5;
    const int lane = t & 31;
    const int h = lane >> 2;
    const int e4 = lane & 3;

    __shared__ float xs[CHUNK * DX];        // 16 KB, row-major
    __shared__ float us[H * 257];           // [h][w][n], stride 257 (bank spread)
    __shared__ float es[H * 33];            // [h][n],    stride 33
    __shared__ float sc[H];

    int s0 = g_segstart[g], s1 = g_segstart[g + 1];
    int len = s1 - s0;
    int per = (len + S_SLICES - 1) / S_SLICES;
    int lo = s0 + s * per;
    int hi = min(lo + per, s1);

    const int eoff = w * 16 + e4 * 4;
    float4 kq = *(const float4*)(g_kq + (h * B_GRAPHS + g) * DX + eoff);

    float4 acc = make_float4(0.f, 0.f, 0.f, 0.f);
    float m_run = -INFINITY, s_run = 0.0f;   // head w state (lane-uniform in warp w)

    const float4* xg = (const float4*)x;

    for (int c0 = lo; c0 < hi; c0 += CHUNK) {
        int cnt = hi - c0;
        int valid = cnt < CHUNK ? cnt : CHUNK;

        // ---- stage 32 node rows (zero-pad beyond valid)
#pragma unroll
        for (int k = 0; k < 4; k++) {
            int f = t + k * 256;          // [0,1024): 32 rows x 32 float4
            int node = f >> 5;
            int c4 = f & 31;
            float4 vv = make_float4(0.f, 0.f, 0.f, 0.f);
            if (node < valid) vv = xg[(size_t)(c0 + node) * 32 + c4];
            *(float4*)(xs + node * DX + c4 * 4) = vv;
        }
        __syncthreads();

        // ---- u-phase: warp w partial dot over its 16 e's, all 32 nodes
#pragma unroll 8
        for (int n = 0; n < CHUNK; n++) {
            float4 xv = *(const float4*)(xs + n * DX + eoff);
            float p = kq.x * xv.x;
            p = fmaf(kq.y, xv.y, p);
            p = fmaf(kq.z, xv.z, p);
            p = fmaf(kq.w, xv.w, p);
            p += __shfl_xor_sync(0xffffffffu, p, 1);
            p += __shfl_xor_sync(0xffffffffu, p, 2);
            if (e4 == 0) us[h * 257 + w * 32 + n] = p;
        }
        __syncthreads();

        // ---- finalize: warp w owns head h2=w; lane = node
        {
            int n = lane;
            float u = us[w * 257 + n];
#pragma unroll
            for (int ww = 1; ww < 8; ww++) u += us[w * 257 + ww * 32 + n];
            if (n >= valid) u = -INFINITY;
            float mc = u;
#pragma unroll
            for (int off = 16; off; off >>= 1)
                mc = fmaxf(mc, __shfl_xor_sync(0xffffffffu, mc, off));
            float m_new = fmaxf(m_run, mc);
            float scale = __expf(m_run - m_new);   // first chunk: exp(-inf)=0
            float en = __expf(u - m_new);          // padded: exp(-inf)=0
            float ssum = en;
#pragma unroll
            for (int off = 16; off; off >>= 1)
                ssum += __shfl_xor_sync(0xffffffffu, ssum, off);
            s_run = fmaf(s_run, scale, ssum);
            m_run = m_new;
            es[w * 33 + n] = en;
            if (n == 0) sc[w] = scale;
        }
        __syncthreads();

        // ---- xa-phase: rescale + accumulate e_n * x[n]
        {
            float scl = sc[h];
            acc.x *= scl; acc.y *= scl; acc.z *= scl; acc.w *= scl;
        }
#pragma unroll 8
        for (int n = 0; n < CHUNK; n++) {
            float a = es[h * 33 + n];
            float4 xv = *(const float4*)(xs + n * DX + eoff);
            acc.x = fmaf(a, xv.x, acc.x);
            acc.y = fmaf(a, xv.y, acc.y);
            acc.z = fmaf(a, xv.z, acc.z);
            acc.w = fmaf(a, xv.w, acc.w);
        }
        __syncthreads();
    }

    // ---- write slice partials
    if (lane == 0) {
        int ims = (s * H + w) * B_GRAPHS + g;
        g_part_m[ims] = m_run;
        g_part_s[ims] = s_run;
    }
    int ip = (s * H + h) * B_GRAPHS + g;
    *(float4*)(g_part_xa + (size_t)ip * DX + eoff) = acc;
}

// ---------------------------------------------------------------------------
// Kernel 4: combine slice partials -> g_xa (already normalized)
// ---------------------------------------------------------------------------
__global__ void k_combine() {
    int h = blockIdx.x / B_GRAPHS;
    int g = blockIdx.x % B_GRAPHS;
    int t = threadIdx.x;

    __shared__ float wgt[S_SLICES];
    __shared__ float inv_s;

    if (t == 0) {
        float ms[S_SLICES], ss[S_SLICES];
#pragma unroll
        for (int i = 0; i < S_SLICES; i++) {
            int idx = (i * H + h) * B_GRAPHS + g;
            ms[i] = g_part_m[idx];
            ss[i] = g_part_s[idx];
        }
        float m = -INFINITY;
#pragma unroll
        for (int i = 0; i < S_SLICES; i++) m = fmaxf(m, ms[i]);
        float ssum = 0.0f;
#pragma unroll
        for (int i = 0; i < S_SLICES; i++) {
            float wi = (m == -INFINITY) ? 0.0f : __expf(ms[i] - m);
            wgt[i] = wi;
            ssum = fmaf(ss[i], wi, ssum);
        }
        inv_s = 1.0f / (ssum + 1e-16f);
    }
    __syncthreads();

    float accv = 0.0f;
#pragma unroll
    for (int i = 0; i < S_SLICES; i++)
        accv = fmaf(g_part_xa[(size_t)((i * H + h) * B_GRAPHS + g) * DX + t], wgt[i], accv);
    g_xa[(h * B_GRAPHS + g) * DX + t] = accv * inv_s;
}

// ---------------------------------------------------------------------------
// Kernel 5: out[b,:] = (sum_h qc*query[h,b] + xa[h,b] @ Wv[h]) @ Wf
// 512 threads: t = (h, v). Per-thread 128-deep column dot (high MLP),
// smem reduce over h, then Wf projection.
// ---------------------------------------------------------------------------
__global__ __launch_bounds__(512) void k_final(const float* __restrict__ Wv,
                        const float* __restrict__ qcoef,
                        const float* __restrict__ Wf,
                        float* __restrict__ out) {
    int b = blockIdx.x;
    int t = threadIdx.x;
    int h = t >> 6;
    int v = t & 63;
    float qc = qcoef[0];

    __shared__ float hpart[H * DV];
    __shared__ float tot[DV];

    {
        int hb = h * B_GRAPHS + b;
        float accv = qc * g_query[hb * DV + v];
        const float* xa = g_xa + hb * DX;
        const float* wv = Wv + h * DX * DV + v;
#pragma unroll 16
        for (int e = 0; e < DX; e++) accv = fmaf(xa[e], wv[e * DV], accv);
        hpart[h * DV + v] = accv;
    }
    __syncthreads();
    if (t < DV) {
        float s = 0.0f;
#pragma unroll
        for (int hh = 0; hh < H; hh++) s += hpart[hh * DV + t];
        tot[t] = s;
    }
    __syncthreads();
    if (t < DOUT) {
        float accv = 0.0f;
#pragma unroll 16
        for (int v2 = 0; v2 < DV; v2++)
            accv = fmaf(tot[v2], Wf[v2 * DOUT + t], accv);
        out[b * DOUT + t] = accv;
    }
}

// ---------------------------------------------------------------------------
extern "C" void kernel_launch(void* const* d_in, const int* in_sizes, int n_in,
                              void* d_out, int out_size) {
    const float* x       = (const float*)d_in[0];
    // d_in[1] = edge_index (unused by the reference math)
    const int*   batch   = (const int*)d_in[2];
    const float* context = (const float*)d_in[3];
    const float* Wq      = (const float*)d_in[4];
    const float* Wk      = (const float*)d_in[5];
    const float* Wv      = (const float*)d_in[6];
    const float* qcoef   = (const float*)d_in[7];
    const float* Wf      = (const float*)d_in[8];
    float* out = (float*)d_out;

    k_init<<<(N_NODES + 255) / 256, 256>>>(batch);
    k_qkq<<<H * B_GRAPHS, 128>>>(context, Wq, Wk);
    dim3 fgrid(S_SLICES, B_GRAPHS);
    k_fused<<<fgrid, 256>>>(x);
    k_combine<<<H * B_GRAPHS, DX>>>();
    k_final<<<B_GRAPHS, 512>>>(Wv, qcoef, Wf, out);
}

// round 4
// speedup vs baseline: 1.9504x; 1.2598x over previous
#include <cuda_runtime.h>
#include <math.h>

#define N_NODES 100000
#define B_GRAPHS 128
#define H 8
#define DC 256
#define DX 128   /* DE+4 */
#define DV 64
#define DOUT 124
#define S_SLICES 8
#define CHUNK 32

// ---- scratch (static device globals; no allocation) ----
__device__ __align__(16) float g_query[H * B_GRAPHS * DV];
__device__ __align__(16) float g_kq[H * B_GRAPHS * DX];
__device__ __align__(16) float g_part_xa[S_SLICES * H * B_GRAPHS * DX]; // 4 MB
__device__ float g_part_m[S_SLICES * H * B_GRAPHS];
__device__ float g_part_s[S_SLICES * H * B_GRAPHS];
__device__ int   g_segstart[B_GRAPHS + 1];

// ---------------------------------------------------------------------------
// Kernel 1: segment boundaries from sorted batch[]
// ---------------------------------------------------------------------------
__global__ void k_init(const int* __restrict__ batch) {
    int i = blockIdx.x * blockDim.x + threadIdx.x;
    if (i < N_NODES) {
        int b  = batch[i];
        int bp = (i == 0) ? -1 : batch[i - 1];
        for (int j = bp + 1; j <= b; j++) g_segstart[j] = i;
        if (i == N_NODES - 1)
            for (int j = b + 1; j <= B_GRAPHS; j++) g_segstart[j] = N_NODES;
    }
}

// ---------------------------------------------------------------------------
// Kernel 2a: query[h,b,v] = context[b] @ Wq[h]   (4-way split-K, 256 thr)
// ---------------------------------------------------------------------------
__global__ __launch_bounds__(256) void k_q(const float* __restrict__ context,
                                           const float* __restrict__ Wq) {
    int h = blockIdx.x / B_GRAPHS;
    int b = blockIdx.x % B_GRAPHS;
    int t = threadIdx.x;
    int part = t >> 6, v = t & 63;
    __shared__ float ctx_s[DC];
    __shared__ float parts[4][DV];

    ctx_s[t] = context[b * DC + t];
    __syncthreads();

    float acc = 0.0f;
    const float* wq = Wq + h * DC * DV + part * 64 * DV + v;
    const float* cs = ctx_s + part * 64;
#pragma unroll 16
    for (int c = 0; c < 64; c++) acc = fmaf(cs[c], wq[c * DV], acc);
    parts[part][v] = acc;
    __syncthreads();

    if (t < DV)
        g_query[(h * B_GRAPHS + b) * DV + t] =
            parts[0][t] + parts[1][t] + parts[2][t] + parts[3][t];
}

// ---------------------------------------------------------------------------
// Kernel 2b: kq[h,b,e] = (Wk[h] @ q)/8 — warp-per-row, coalesced row dots
// 128 threads = 4 warps, each warp 32 rows.
// ---------------------------------------------------------------------------
__global__ __launch_bounds__(128) void k_kq(const float* __restrict__ Wk) {
    int h = blockIdx.x / B_GRAPHS;
    int b = blockIdx.x % B_GRAPHS;
    int t = threadIdx.x, w = t >> 5, lane = t & 31;
    __shared__ float q_s[DV];

    if (t < DV) q_s[t] = g_query[(h * B_GRAPHS + b) * DV + t];
    __syncthreads();

    float q0 = q_s[lane], q1 = q_s[lane + 32];
    const float* wk = Wk + h * DX * DV;
    float* kq = g_kq + (h * B_GRAPHS + b) * DX;

#pragma unroll 8
    for (int r = 0; r < 32; r++) {
        int e = w * 32 + r;
        float p = wk[e * DV + lane] * q0;
        p = fmaf(wk[e * DV + 32 + lane], q1, p);
#pragma unroll
        for (int off = 16; off; off >>= 1)
            p += __shfl_xor_sync(0xffffffffu, p, off);
        if (lane == 0) kq[e] = p * 0.125f;  // 1/sqrt(64)
    }
}

// ---------------------------------------------------------------------------
// Kernel 3 (fused): one pass over x per (slice, graph) block with register
// double-buffering of the x stage. Warp w owns e-range [16w,16w+16);
// lane=(h,e4). Online softmax finalized per chunk by warp h.
// ---------------------------------------------------------------------------
__global__ __launch_bounds__(256) void k_fused(const float* __restrict__ x) {
    const int s = blockIdx.x;
    const int g = blockIdx.y;
    const int t = threadIdx.x;
    const int w = t >> 5;
    const int lane = t & 31;
    const int h = lane >> 2;
    const int e4 = lane & 3;

    __shared__ float xs[CHUNK * DX];        // 16 KB
    __shared__ float us[H * 257];           // [head][producer_warp][n]
    __shared__ float es[H * 33];
    __shared__ float sc[H];

    int s0 = g_segstart[g], s1 = g_segstart[g + 1];
    int len = s1 - s0;
    int per = (len + S_SLICES - 1) / S_SLICES;
    int lo = s0 + s * per;
    int hi = min(lo + per, s1);

    const int eoff = w * 16 + e4 * 4;
    float4 kq = *(const float4*)(g_kq + (h * B_GRAPHS + g) * DX + eoff);

    float4 acc = make_float4(0.f, 0.f, 0.f, 0.f);
    float m_run = -INFINITY, s_run = 0.0f;

    const float4* xg = (const float4*)x;

    // per-thread staging slots: f_k = t + 256k -> (node = f>>5, c4 = f&31)
    const int n0 = t >> 5,        c40 = t & 31;
    const int n1 = (t + 256) >> 5, c41 = t & 31;
    const int n2 = (t + 512) >> 5, c42 = t & 31;
    const int n3 = (t + 768) >> 5, c43 = t & 31;

    if (lo < hi) {
        float4 r0, r1, r2, r3;
        const float4 z = make_float4(0.f, 0.f, 0.f, 0.f);
        {
            int valid = min(CHUNK, hi - lo);
            size_t base = (size_t)lo * 32;
            r0 = (n0 < valid) ? xg[base + (size_t)n0 * 32 + c40] : z;
            r1 = (n1 < valid) ? xg[base + (size_t)n1 * 32 + c41] : z;
            r2 = (n2 < valid) ? xg[base + (size_t)n2 * 32 + c42] : z;
            r3 = (n3 < valid) ? xg[base + (size_t)n3 * 32 + c43] : z;
        }

        for (int c0 = lo; c0 < hi; c0 += CHUNK) {
            int valid = min(CHUNK, hi - c0);

            // ---- commit prefetched chunk to smem
            *(float4*)(xs + n0 * DX + c40 * 4) = r0;
            *(float4*)(xs + n1 * DX + c41 * 4) = r1;
            *(float4*)(xs + n2 * DX + c42 * 4) = r2;
            *(float4*)(xs + n3 * DX + c43 * 4) = r3;
            __syncthreads();

            // ---- prefetch next chunk (overlaps with compute below)
            int cn = c0 + CHUNK;
            if (cn < hi) {
                int nv = min(CHUNK, hi - cn);
                size_t base = (size_t)cn * 32;
                r0 = (n0 < nv) ? xg[base + (size_t)n0 * 32 + c40] : z;
                r1 = (n1 < nv) ? xg[base + (size_t)n1 * 32 + c41] : z;
                r2 = (n2 < nv) ? xg[base + (size_t)n2 * 32 + c42] : z;
                r3 = (n3 < nv) ? xg[base + (size_t)n3 * 32 + c43] : z;
            }

            // ---- u-phase: warp w partial dots over its 16 e's
#pragma unroll 8
            for (int n = 0; n < CHUNK; n++) {
                float4 xv = *(const float4*)(xs + n * DX + eoff);
                float p = kq.x * xv.x;
                p = fmaf(kq.y, xv.y, p);
                p = fmaf(kq.z, xv.z, p);
                p = fmaf(kq.w, xv.w, p);
                p += __shfl_xor_sync(0xffffffffu, p, 1);
                p += __shfl_xor_sync(0xffffffffu, p, 2);
                if (e4 == 0) us[h * 257 + w * 32 + n] = p;
            }
            __syncthreads();

            // ---- finalize: warp w owns head w; lane = node
            {
                int n = lane;
                float u = us[w * 257 + n];
#pragma unroll
                for (int ww = 1; ww < 8; ww++) u += us[w * 257 + ww * 32 + n];
                if (n >= valid) u = -INFINITY;
                float mc = u;
#pragma unroll
                for (int off = 16; off; off >>= 1)
                    mc = fmaxf(mc, __shfl_xor_sync(0xffffffffu, mc, off));
                float m_new = fmaxf(m_run, mc);
                float scale = __expf(m_run - m_new);
                float en = __expf(u - m_new);
                float ssum = en;
#pragma unroll
                for (int off = 16; off; off >>= 1)
                    ssum += __shfl_xor_sync(0xffffffffu, ssum, off);
                s_run = fmaf(s_run, scale, ssum);
                m_run = m_new;
                es[w * 33 + n] = en;
                if (n == 0) sc[w] = scale;
            }
            __syncthreads();

            // ---- xa-phase: rescale + accumulate
            {
                float scl = sc[h];
                acc.x *= scl; acc.y *= scl; acc.z *= scl; acc.w *= scl;
            }
#pragma unroll 8
            for (int n = 0; n < CHUNK; n++) {
                float a = es[h * 33 + n];
                float4 xv = *(const float4*)(xs + n * DX + eoff);
                acc.x = fmaf(a, xv.x, acc.x);
                acc.y = fmaf(a, xv.y, acc.y);
                acc.z = fmaf(a, xv.z, acc.z);
                acc.w = fmaf(a, xv.w, acc.w);
            }
            __syncthreads();
        }
    }

    if (lane == 0) {
        int ims = (s * H + w) * B_GRAPHS + g;
        g_part_m[ims] = m_run;
        g_part_s[ims] = s_run;
    }
    int ip = (s * H + h) * B_GRAPHS + g;
    *(float4*)(g_part_xa + (size_t)ip * DX + eoff) = acc;
}

// ---------------------------------------------------------------------------
// Kernel 4 (merged combine + final): one block per graph, 1024 threads.
//   combine: t=(h,e) normalizes slice partials into smem xa_s
//   final:   t=(h,v) -> hpart, reduce over h, project with Wf
// ---------------------------------------------------------------------------
__global__ __launch_bounds__(1024) void k_cf(const float* __restrict__ Wv,
                                             const float* __restrict__ qcoef,
                                             const float* __restrict__ Wf,
                                             float* __restrict__ out) {
    int g = blockIdx.x;
    int t = threadIdx.x;
    int h = t >> 7, e = t & 127;

    __shared__ float wgt[H][S_SLICES];
    __shared__ float inv_s[H];
    __shared__ float xa_s[H][DX];
    __shared__ float hpart[H][DV];
    __shared__ float tot[DV];

    if (e == 0) {  // one thread per head
        float ms[S_SLICES], ss[S_SLICES];
#pragma unroll
        for (int i = 0; i < S_SLICES; i++) {
            int idx = (i * H + h) * B_GRAPHS + g;
            ms[i] = g_part_m[idx];
            ss[i] = g_part_s[idx];
        }
        float m = -INFINITY;
#pragma unroll
        for (int i = 0; i < S_SLICES; i++) m = fmaxf(m, ms[i]);
        float ssum = 0.0f;
#pragma unroll
        for (int i = 0; i < S_SLICES; i++) {
            float wi = (ms[i] == -INFINITY) ? 0.0f : __expf(ms[i] - m);
            wgt[h][i] = wi;
            ssum = fmaf(ss[i], wi, ssum);
        }
        inv_s[h] = 1.0f / (ssum + 1e-16f);
    }
    __syncthreads();

    {
        float accv = 0.0f;
#pragma unroll
        for (int i = 0; i < S_SLICES; i++)
            accv = fmaf(g_part_xa[(size_t)((i * H + h) * B_GRAPHS + g) * DX + e],
                        wgt[h][i], accv);
        xa_s[h][e] = accv * inv_s[h];
    }
    __syncthreads();

    if (t < 512) {
        int h2 = t >> 6, v = t & 63;
        float accv = qcoef[0] * g_query[(h2 * B_GRAPHS + g) * DV + v];
        const float* wv = Wv + h2 * DX * DV + v;
        const float* xa = xa_s[h2];
#pragma unroll 16
        for (int e2 = 0; e2 < DX; e2++) accv = fmaf(xa[e2], wv[e2 * DV], accv);
        hpart[h2][v] = accv;
    }
    __syncthreads();

    if (t < DV) {
        float sum = 0.0f;
#pragma unroll
        for (int hh = 0; hh < H; hh++) sum += hpart[hh][t];
        tot[t] = sum;
    }
    __syncthreads();

    if (t < DOUT) {
        float accv = 0.0f;
#pragma unroll 16
        for (int v2 = 0; v2 < DV; v2++)
            accv = fmaf(tot[v2], Wf[v2 * DOUT + t], accv);
        out[g * DOUT + t] = accv;
    }
}

// ---------------------------------------------------------------------------
extern "C" void kernel_launch(void* const* d_in, const int* in_sizes, int n_in,
                              void* d_out, int out_size) {
    const float* x       = (const float*)d_in[0];
    // d_in[1] = edge_index (unused by the reference math)
    const int*   batch   = (const int*)d_in[2];
    const float* context = (const float*)d_in[3];
    const float* Wq      = (const float*)d_in[4];
    const float* Wk      = (const float*)d_in[5];
    const float* Wv      = (const float*)d_in[6];
    const float* qcoef   = (const float*)d_in[7];
    const float* Wf      = (const float*)d_in[8];
    float* out = (float*)d_out;

    k_init<<<(N_NODES + 255) / 256, 256>>>(batch);
    k_q<<<H * B_GRAPHS, 256>>>(context, Wq);
    k_kq<<<H * B_GRAPHS, 128>>>(Wk);
    dim3 fgrid(S_SLICES, B_GRAPHS);
    k_fused<<<fgrid, 256>>>(x);          // launch #4 -> profiled
    k_cf<<<B_GRAPHS, 1024>>>(Wv, qcoef, Wf, out);
}

// round 5
// speedup vs baseline: 2.9738x; 1.5247x over previous
#include <cuda_runtime.h>
#include <math.h>

#define N_NODES 100000
#define B_GRAPHS 128
#define H 8
#define DC 256
#define DX 128   /* DE+4 */
#define DV 64
#define DOUT 124
#define S_SLICES 4
#define CHUNK 32
#define GB 4     /* graphs per block in k_q / k_kq */

// ---- scratch (static device globals; no allocation) ----
__device__ __align__(16) float g_query[H * B_GRAPHS * DV];
__device__ __align__(16) float g_kq[H * B_GRAPHS * DX];
__device__ __align__(16) float g_part_xa[S_SLICES * H * B_GRAPHS * DX]; // 2 MB
__device__ float g_part_m[S_SLICES * H * B_GRAPHS];
__device__ float g_part_s[S_SLICES * H * B_GRAPHS];
__device__ int   g_segstart[B_GRAPHS + 1];

// ---------------------------------------------------------------------------
// Kernel 1: segment boundaries from sorted batch[]
// ---------------------------------------------------------------------------
__global__ void k_init(const int* __restrict__ batch) {
    int i = blockIdx.x * blockDim.x + threadIdx.x;
    if (i < N_NODES) {
        int b  = batch[i];
        int bp = (i == 0) ? -1 : batch[i - 1];
        for (int j = bp + 1; j <= b; j++) g_segstart[j] = i;
        if (i == N_NODES - 1)
            for (int j = b + 1; j <= B_GRAPHS; j++) g_segstart[j] = N_NODES;
    }
}

// ---------------------------------------------------------------------------
// Kernel 2a: query[h,b,v] = context[b] @ Wq[h]; 4 graphs per block
// block = (h, graph-quad), 256 threads = (part, v)
// ---------------------------------------------------------------------------
__global__ __launch_bounds__(256) void k_q(const float* __restrict__ context,
                                           const float* __restrict__ Wq) {
    int h  = blockIdx.x >> 5;
    int gq = blockIdx.x & 31;
    int t = threadIdx.x;
    int part = t >> 6, v = t & 63;

    __shared__ float ctx_s[GB][DC];
    __shared__ float parts[4][GB][DV];

#pragma unroll
    for (int i = t; i < GB * DC; i += 256)
        ctx_s[i >> 8][i & 255] = context[(gq * GB + (i >> 8)) * DC + (i & 255)];
    __syncthreads();

    float a0 = 0.f, a1 = 0.f, a2 = 0.f, a3 = 0.f;
    const float* wq = Wq + h * DC * DV + part * 64 * DV + v;
    const float* c0 = &ctx_s[0][part * 64];
    const float* c1 = &ctx_s[1][part * 64];
    const float* c2 = &ctx_s[2][part * 64];
    const float* c3 = &ctx_s[3][part * 64];
#pragma unroll 8
    for (int c = 0; c < 64; c++) {
        float wv = wq[c * DV];
        a0 = fmaf(c0[c], wv, a0);
        a1 = fmaf(c1[c], wv, a1);
        a2 = fmaf(c2[c], wv, a2);
        a3 = fmaf(c3[c], wv, a3);
    }
    parts[part][0][v] = a0;
    parts[part][1][v] = a1;
    parts[part][2][v] = a2;
    parts[part][3][v] = a3;
    __syncthreads();

    {
        int b4 = t >> 6;   // reuse 256 threads as (b4, v)
        float q = parts[0][b4][v] + parts[1][b4][v] + parts[2][b4][v] + parts[3][b4][v];
        g_query[(h * B_GRAPHS + gq * GB + b4) * DV + v] = q;
    }
}

// ---------------------------------------------------------------------------
// Kernel 2b: kq[h,b,e] = (Wk[h] @ q)/8; 4 graphs per block, warp-per-row
// block = (h, graph-quad), 128 threads = 4 warps, warp w covers 32 rows
// ---------------------------------------------------------------------------
__global__ __launch_bounds__(128) void k_kq(const float* __restrict__ Wk) {
    int h  = blockIdx.x >> 5;
    int gq = blockIdx.x & 31;
    int t = threadIdx.x, w = t >> 5, lane = t & 31;

    __shared__ float q_s[GB][DV];
#pragma unroll
    for (int i = t; i < GB * DV; i += 128)
        q_s[i >> 6][i & 63] = g_query[(h * B_GRAPHS + gq * GB + (i >> 6)) * DV + (i & 63)];
    __syncthreads();

    float q00 = q_s[0][lane], q01 = q_s[0][lane + 32];
    float q10 = q_s[1][lane], q11 = q_s[1][lane + 32];
    float q20 = q_s[2][lane], q21 = q_s[2][lane + 32];
    float q30 = q_s[3][lane], q31 = q_s[3][lane + 32];

    const float* wk = Wk + h * DX * DV;
#pragma unroll 4
    for (int r = 0; r < 32; r++) {
        int e = w * 32 + r;
        float w0 = wk[e * DV + lane];
        float w1 = wk[e * DV + 32 + lane];
        float p0 = fmaf(w0, q00, w1 * q01);
        float p1 = fmaf(w0, q10, w1 * q11);
        float p2 = fmaf(w0, q20, w1 * q21);
        float p3 = fmaf(w0, q30, w1 * q31);
#pragma unroll
        for (int off = 16; off; off >>= 1) {
            p0 += __shfl_xor_sync(0xffffffffu, p0, off);
            p1 += __shfl_xor_sync(0xffffffffu, p1, off);
            p2 += __shfl_xor_sync(0xffffffffu, p2, off);
            p3 += __shfl_xor_sync(0xffffffffu, p3, off);
        }
        float pv = (lane & 2) ? ((lane & 1) ? p3 : p2) : ((lane & 1) ? p1 : p0);
        if (lane < 4)
            g_kq[(h * B_GRAPHS + gq * GB + lane) * DX + e] = pv * 0.125f;
    }
}

// ---------------------------------------------------------------------------
// Kernel 3 (fused): register-resident single pass over x.
// Warp w owns chunk nodes {w, w+8, w+16, w+24}; lane = float4 fragment.
// kq for all 8 heads in registers; 8 per-thread float4 xa accumulators.
// Smem only for u exchange / softmax coefficients / final block reduce.
// ---------------------------------------------------------------------------
__global__ __launch_bounds__(256, 2) void k_fused(const float* __restrict__ x) {
    const int s = blockIdx.x;
    const int g = blockIdx.y;
    const int t = threadIdx.x;
    const int w = t >> 5;
    const int lane = t & 31;

    __shared__ float us[H * 33];                       // [h][n]
    __shared__ __align__(16) float es[CHUNK * H];      // [n][h]
    __shared__ __align__(16) float sc[H];
    __shared__ __align__(16) float buf[H * H * DX];    // 32 KB: [w][h][e]

    int s0 = g_segstart[g], s1 = g_segstart[g + 1];
    int len = s1 - s0;
    int per = (len + S_SLICES - 1) / S_SLICES;
    int lo = s0 + s * per;
    int hi = min(lo + per, s1);

    float4 kq[H];
#pragma unroll
    for (int h = 0; h < H; h++)
        kq[h] = *(const float4*)(g_kq + (h * B_GRAPHS + g) * DX + lane * 4);

    float4 acc[H];
#pragma unroll
    for (int h = 0; h < H; h++) acc[h] = make_float4(0.f, 0.f, 0.f, 0.f);

    float m_run = -INFINITY, s_run = 0.0f;   // per-warp head-w state

    const float4* xg = (const float4*)x;
    const float4 z = make_float4(0.f, 0.f, 0.f, 0.f);
    float4 cur[4], nxt[4];

    if (lo < hi) {
        int valid = min(CHUNK, hi - lo);
#pragma unroll
        for (int k = 0; k < 4; k++) {
            int n = w + 8 * k;
            cur[k] = (n < valid) ? xg[(size_t)(lo + n) * 32 + lane] : z;
        }
    }

    for (int c0 = lo; c0 < hi; c0 += CHUNK) {
        int valid = min(CHUNK, hi - c0);
        int cn = c0 + CHUNK;
        if (cn < hi) {
            int nv = min(CHUNK, hi - cn);
#pragma unroll
            for (int k = 0; k < 4; k++) {
                int n = w + 8 * k;
                nxt[k] = (n < nv) ? xg[(size_t)(cn + n) * 32 + lane] : z;
            }
        }

        // ---- u-phase: 8 head dots per owned node, register-only x
#pragma unroll
        for (int k = 0; k < 4; k++) {
            int n = w + 8 * k;
            float4 xv = cur[k];
            float p0 = fmaf(kq[0].x, xv.x, fmaf(kq[0].y, xv.y, fmaf(kq[0].z, xv.z, kq[0].w * xv.w)));
            float p1 = fmaf(kq[1].x, xv.x, fmaf(kq[1].y, xv.y, fmaf(kq[1].z, xv.z, kq[1].w * xv.w)));
            float p2 = fmaf(kq[2].x, xv.x, fmaf(kq[2].y, xv.y, fmaf(kq[2].z, xv.z, kq[2].w * xv.w)));
            float p3 = fmaf(kq[3].x, xv.x, fmaf(kq[3].y, xv.y, fmaf(kq[3].z, xv.z, kq[3].w * xv.w)));
            float p4 = fmaf(kq[4].x, xv.x, fmaf(kq[4].y, xv.y, fmaf(kq[4].z, xv.z, kq[4].w * xv.w)));
            float p5 = fmaf(kq[5].x, xv.x, fmaf(kq[5].y, xv.y, fmaf(kq[5].z, xv.z, kq[5].w * xv.w)));
            float p6 = fmaf(kq[6].x, xv.x, fmaf(kq[6].y, xv.y, fmaf(kq[6].z, xv.z, kq[6].w * xv.w)));
            float p7 = fmaf(kq[7].x, xv.x, fmaf(kq[7].y, xv.y, fmaf(kq[7].z, xv.z, kq[7].w * xv.w)));
#pragma unroll
            for (int off = 1; off <= 2; off <<= 1) {
                p0 += __shfl_xor_sync(0xffffffffu, p0, off);
                p1 += __shfl_xor_sync(0xffffffffu, p1, off);
                p2 += __shfl_xor_sync(0xffffffffu, p2, off);
                p3 += __shfl_xor_sync(0xffffffffu, p3, off);
                p4 += __shfl_xor_sync(0xffffffffu, p4, off);
                p5 += __shfl_xor_sync(0xffffffffu, p5, off);
                p6 += __shfl_xor_sync(0xffffffffu, p6, off);
                p7 += __shfl_xor_sync(0xffffffffu, p7, off);
            }
            int j = lane & 3;
            float ra = (j & 2) ? ((j & 1) ? p6 : p4) : ((j & 1) ? p2 : p0);
            float rb = (j & 2) ? ((j & 1) ? p7 : p5) : ((j & 1) ? p3 : p1);
#pragma unroll
            for (int off = 4; off <= 16; off <<= 1) {
                ra += __shfl_xor_sync(0xffffffffu, ra, off);
                rb += __shfl_xor_sync(0xffffffffu, rb, off);
            }
            float uw = (lane >> 2) ? rb : ra;
            if (lane < 8)
                us[(2 * (lane & 3) + (lane >> 2)) * 33 + n] = uw;
        }
        __syncthreads();

        // ---- finalize: warp w owns head w; lane = node
        {
            int n = lane;
            float u = us[w * 33 + n];
            if (n >= valid) u = -INFINITY;
            float mc = u;
#pragma unroll
            for (int off = 16; off; off >>= 1)
                mc = fmaxf(mc, __shfl_xor_sync(0xffffffffu, mc, off));
            float m_new = fmaxf(m_run, mc);
            float scale = __expf(m_run - m_new);
            float en = __expf(u - m_new);
            float ssum = en;
#pragma unroll
            for (int off = 16; off; off >>= 1)
                ssum += __shfl_xor_sync(0xffffffffu, ssum, off);
            s_run = fmaf(s_run, scale, ssum);
            m_run = m_new;
            es[n * H + w] = en;
            if (n == 0) sc[w] = scale;
        }
        __syncthreads();

        // ---- xa-phase: rescale + accumulate from registers
        {
            float4 s0v = *(const float4*)sc;
            float4 s1v = *(const float4*)(sc + 4);
            acc[0].x *= s0v.x; acc[0].y *= s0v.x; acc[0].z *= s0v.x; acc[0].w *= s0v.x;
            acc[1].x *= s0v.y; acc[1].y *= s0v.y; acc[1].z *= s0v.y; acc[1].w *= s0v.y;
            acc[2].x *= s0v.z; acc[2].y *= s0v.z; acc[2].z *= s0v.z; acc[2].w *= s0v.z;
            acc[3].x *= s0v.w; acc[3].y *= s0v.w; acc[3].z *= s0v.w; acc[3].w *= s0v.w;
            acc[4].x *= s1v.x; acc[4].y *= s1v.x; acc[4].z *= s1v.x; acc[4].w *= s1v.x;
            acc[5].x *= s1v.y; acc[5].y *= s1v.y; acc[5].z *= s1v.y; acc[5].w *= s1v.y;
            acc[6].x *= s1v.z; acc[6].y *= s1v.z; acc[6].z *= s1v.z; acc[6].w *= s1v.z;
            acc[7].x *= s1v.w; acc[7].y *= s1v.w; acc[7].z *= s1v.w; acc[7].w *= s1v.w;
        }
#pragma unroll
        for (int k = 0; k < 4; k++) {
            int n = w + 8 * k;
            float4 alo = *(const float4*)(es + n * H);
            float4 ahi = *(const float4*)(es + n * H + 4);
            float4 xv = cur[k];
            acc[0].x = fmaf(alo.x, xv.x, acc[0].x); acc[0].y = fmaf(alo.x, xv.y, acc[0].y);
            acc[0].z = fmaf(alo.x, xv.z, acc[0].z); acc[0].w = fmaf(alo.x, xv.w, acc[0].w);
            acc[1].x = fmaf(alo.y, xv.x, acc[1].x); acc[1].y = fmaf(alo.y, xv.y, acc[1].y);
            acc[1].z = fmaf(alo.y, xv.z, acc[1].z); acc[1].w = fmaf(alo.y, xv.w, acc[1].w);
            acc[2].x = fmaf(alo.z, xv.x, acc[2].x); acc[2].y = fmaf(alo.z, xv.y, acc[2].y);
            acc[2].z = fmaf(alo.z, xv.z, acc[2].z); acc[2].w = fmaf(alo.z, xv.w, acc[2].w);
            acc[3].x = fmaf(alo.w, xv.x, acc[3].x); acc[3].y = fmaf(alo.w, xv.y, acc[3].y);
            acc[3].z = fmaf(alo.w, xv.z, acc[3].z); acc[3].w = fmaf(alo.w, xv.w, acc[3].w);
            acc[4].x = fmaf(ahi.x, xv.x, acc[4].x); acc[4].y = fmaf(ahi.x, xv.y, acc[4].y);
            acc[4].z = fmaf(ahi.x, xv.z, acc[4].z); acc[4].w = fmaf(ahi.x, xv.w, acc[4].w);
            acc[5].x = fmaf(ahi.y, xv.x, acc[5].x); acc[5].y = fmaf(ahi.y, xv.y, acc[5].y);
            acc[5].z = fmaf(ahi.y, xv.z, acc[5].z); acc[5].w = fmaf(ahi.y, xv.w, acc[5].w);
            acc[6].x = fmaf(ahi.z, xv.x, acc[6].x); acc[6].y = fmaf(ahi.z, xv.y, acc[6].y);
            acc[6].z = fmaf(ahi.z, xv.z, acc[6].z); acc[6].w = fmaf(ahi.z, xv.w, acc[6].w);
            acc[7].x = fmaf(ahi.w, xv.x, acc[7].x); acc[7].y = fmaf(ahi.w, xv.y, acc[7].y);
            acc[7].z = fmaf(ahi.w, xv.z, acc[7].z); acc[7].w = fmaf(ahi.w, xv.w, acc[7].w);
        }

#pragma unroll
        for (int k = 0; k < 4; k++) cur[k] = nxt[k];
    }

    // ---- slice m/s partials
    if (lane == 0) {
        int ims = (s * H + w) * B_GRAPHS + g;
        g_part_m[ims] = m_run;
        g_part_s[ims] = s_run;
    }

    // ---- cross-warp xa reduction via smem buffer, then store partials
#pragma unroll
    for (int h = 0; h < H; h++)
        *(float4*)(buf + ((w * H + h) * 32 + lane) * 4) = acc[h];
    __syncthreads();
    {
        int h = t >> 5, fr = lane;
        float4 sum = z;
#pragma unroll
        for (int ww = 0; ww < H; ww++) {
            float4 v = *(const float4*)(buf + ((ww * H + h) * 32 + fr) * 4);
            sum.x += v.x; sum.y += v.y; sum.z += v.z; sum.w += v.w;
        }
        *(float4*)(g_part_xa + (size_t)((s * H + h) * B_GRAPHS + g) * DX + fr * 4) = sum;
    }
}

// ---------------------------------------------------------------------------
// Kernel 4 (merged combine + final): one block per graph, 1024 threads.
// ---------------------------------------------------------------------------
__global__ __launch_bounds__(1024) void k_cf(const float* __restrict__ Wv,
                                             const float* __restrict__ qcoef,
                                             const float* __restrict__ Wf,
                                             float* __restrict__ out) {
    int g = blockIdx.x;
    int t = threadIdx.x;
    int h = t >> 7, e = t & 127;

    __shared__ float wgt[H][S_SLICES];
    __shared__ float inv_s[H];
    __shared__ float xa_s[H][DX];
    __shared__ float hpart[H][DV];
    __shared__ float tot[DV];

    if (e == 0) {
        float ms[S_SLICES], ss[S_SLICES];
#pragma unroll
        for (int i = 0; i < S_SLICES; i++) {
            int idx = (i * H + h) * B_GRAPHS + g;
            ms[i] = g_part_m[idx];
            ss[i] = g_part_s[idx];
        }
        float m = -INFINITY;
#pragma unroll
        for (int i = 0; i < S_SLICES; i++) m = fmaxf(m, ms[i]);
        float ssum = 0.0f;
#pragma unroll
        for (int i = 0; i < S_SLICES; i++) {
            float wi = (ms[i] == -INFINITY) ? 0.0f : __expf(ms[i] - m);
            wgt[h][i] = wi;
            ssum = fmaf(ss[i], wi, ssum);
        }
        inv_s[h] = 1.0f / (ssum + 1e-16f);
    }
    __syncthreads();

    {
        float accv = 0.0f;
#pragma unroll
        for (int i = 0; i < S_SLICES; i++)
            accv = fmaf(g_part_xa[(size_t)((i * H + h) * B_GRAPHS + g) * DX + e],
                        wgt[h][i], accv);
        xa_s[h][e] = accv * inv_s[h];
    }
    __syncthreads();

    if (t < 512) {
        int h2 = t >> 6, v = t & 63;
        float accv = qcoef[0] * g_query[(h2 * B_GRAPHS + g) * DV + v];
        const float* wv = Wv + h2 * DX * DV + v;
        const float* xa = xa_s[h2];
#pragma unroll 16
        for (int e2 = 0; e2 < DX; e2++) accv = fmaf(xa[e2], wv[e2 * DV], accv);
        hpart[h2][v] = accv;
    }
    __syncthreads();

    if (t < DV) {
        float sum = 0.0f;
#pragma unroll
        for (int hh = 0; hh < H; hh++) sum += hpart[hh][t];
        tot[t] = sum;
    }
    __syncthreads();

    if (t < DOUT) {
        float accv = 0.0f;
#pragma unroll 16
        for (int v2 = 0; v2 < DV; v2++)
            accv = fmaf(tot[v2], Wf[v2 * DOUT + t], accv);
        out[g * DOUT + t] = accv;
    }
}

// ---------------------------------------------------------------------------
extern "C" void kernel_launch(void* const* d_in, const int* in_sizes, int n_in,
                              void* d_out, int out_size) {
    const float* x       = (const float*)d_in[0];
    // d_in[1] = edge_index (unused by the reference math)
    const int*   batch   = (const int*)d_in[2];
    const float* context = (const float*)d_in[3];
    const float* Wq      = (const float*)d_in[4];
    const float* Wk      = (const float*)d_in[5];
    const float* Wv      = (const float*)d_in[6];
    const float* qcoef   = (const float*)d_in[7];
    const float* Wf      = (const float*)d_in[8];
    float* out = (float*)d_out;

    k_init<<<(N_NODES + 255) / 256, 256>>>(batch);
    k_q<<<H * 32, 256>>>(context, Wq);
    k_kq<<<H * 32, 128>>>(Wk);
    dim3 fgrid(S_SLICES, B_GRAPHS);
    k_fused<<<fgrid, 256>>>(x);          // launch #4 -> profiled
    k_cf<<<B_GRAPHS, 1024>>>(Wv, qcoef, Wf, out);
}